// round 15
// baseline (speedup 1.0000x reference)
#include <cuda_runtime.h>
#include <cuda_fp16.h>
#include <cuda_fp8.h>

#define FLAT 12288
#define HID  4096
#define NS   16
#define KST  4
#define LRf  0.01f
#define LRh  0.005f      // 0.5 * LR, folded into tanh-form sigmoid
#define RCH1 96          // 128-row chunks in fused conv pass
#define RCH2 192         // 64-row chunks in fp8 gemvT passes
#define WSCL 128.f       // fp8 storage scale (W*128); 1/128 folded into v/h
#define WINV (1.f / 128.f)
#define CTH  1024        // cheap-phase threads (single block)
#define VPT  (FLAT / CTH)   // 12 v-elements per thread
#define HPT  (HID / CTH)    // 4 h-elements per thread

// ---------------- device scratch (static, no runtime allocation) ----------------
__device__ unsigned char g_W8[(size_t)FLAT * HID];  // fp8 e4m3 copy of 128*W (48 MB)
__device__ float g_part[RCH2 * HID];  // gemvT partial column sums
__device__ float g_h[HID];            // dense-phase working h
__device__ float g_hA[HID];           // hinit_0 (q)
__device__ float g_hB[HID];           // hfinal_0 (s)
__device__ float g_vA[FLAT];          // vfinal_0 (r)

__device__ __forceinline__ float sigm(float x) { return 1.f / (1.f + __expf(-x)); }
__device__ __forceinline__ float tanha(float x) {
    float y;
    asm("tanh.approx.f32 %0, %1;" : "=f"(y) : "f"(x));
    return y;
}
__device__ __forceinline__ float2 fp8x2_to_f2(unsigned short s) {
    __half2_raw hr = __nv_cvt_fp8x2_to_halfraw2((__nv_fp8x2_storage_t)s, __NV_E4M3);
    return __half22float2(*reinterpret_cast<__half2*>(&hr));
}

// ---------------- dense phase: sample 0 ----------------

// Pass 1 of gemvT, fused with W->fp8 conversion: reads fp32 W (200MB) once,
// emits fp8 copy of 128*W (48MB) and partial column sums. grid (8, 96).
__global__ void k_gemvT_conv(const float* __restrict__ W, const float* __restrict__ v) {
    __shared__ float sv[128];
    int r0 = blockIdx.y * 128;
    if (threadIdx.x < 128) sv[threadIdx.x] = v[r0 + threadIdx.x];
    __syncthreads();
    int col2 = blockIdx.x * 256 + threadIdx.x;      // 2-col group index
    const float2* Wp = (const float2*)W + (size_t)r0 * (HID / 2) + col2;
    unsigned short* W8p = (unsigned short*)g_W8 + (size_t)r0 * (HID / 2) + col2;
    float ax = 0.f, ay = 0.f;
#pragma unroll 8
    for (int r = 0; r < 128; r++) {
        float2 w = Wp[(size_t)r * (HID / 2)];
        float2 wsc; wsc.x = w.x * WSCL; wsc.y = w.y * WSCL;
        W8p[(size_t)r * (HID / 2)] =
            (unsigned short)__nv_cvt_float2_to_fp8x2(wsc, __NV_SATFINITE, __NV_E4M3);
        float s = sv[r];
        ax += w.x * s;
        ay += w.y * s;
    }
    float2 o; o.x = ax; o.y = ay;
    ((float2*)g_part)[blockIdx.y * (HID / 2) + col2] = o;
}

// Passes 2..4: fp8 W. Thread loads uint (4 weights) per row over 64 rows.
// grid (4, 192) = 768 blocks. sv pre-scaled by 1/128.
__global__ void k_gemvT(const float* __restrict__ v) {
    __shared__ float sv[64];
    int r0 = blockIdx.y * 64;
    if (threadIdx.x < 64) sv[threadIdx.x] = v[r0 + threadIdx.x] * WINV;
    __syncthreads();
    int col4 = blockIdx.x * 256 + threadIdx.x;      // 4-col group index
    const unsigned* Wp = (const unsigned*)g_W8 + (size_t)r0 * (HID / 4) + col4;
    float a0 = 0.f, a1 = 0.f, a2 = 0.f, a3 = 0.f;
#pragma unroll 8
    for (int r = 0; r < 64; r++) {
        unsigned w = Wp[(size_t)r * (HID / 4)];
        float2 f0 = fp8x2_to_f2((unsigned short)(w & 0xffffu));
        float2 f1 = fp8x2_to_f2((unsigned short)(w >> 16));
        float s = sv[r];
        a0 += f0.x * s; a1 += f0.y * s; a2 += f1.x * s; a3 += f1.y * s;
    }
    float4 o; o.x = a0; o.y = a1; o.z = a2; o.w = a3;
    ((float4*)g_part)[blockIdx.y * (HID / 4) + col4] = o;
}

// reduce partials + bias + sigmoid -> g_h; optionally save hinit/hfinal
__global__ void k_hred(const float* __restrict__ b, int save, int nch) {
    int j = blockIdx.x * 256 + threadIdx.x;
    float s = b[j];
#pragma unroll 8
    for (int r = 0; r < nch; r++) s += g_part[r * HID + j];
    float h = sigm(s);
    g_h[j] = h;
    if (save == 1) g_hA[j] = h;        // hinit_0 (q for sample 1)
    else if (save == 2) g_hB[j] = h;   // hfinal_0 (s for sample 1)
}

// v = sigmoid(a + W h): one warp per row, 16 rows per 512-thread block.
// uint4 loads = 16 fp8 weights per LDG. sh pre-scaled by 1/128.
__global__ void k_gemv(const float* __restrict__ a) {
    __shared__ float sh[HID];
    for (int k = threadIdx.x; k < HID; k += blockDim.x) sh[k] = g_h[k] * WINV;
    __syncthreads();
    int warp = threadIdx.x >> 5, lane = threadIdx.x & 31;
    int row = blockIdx.x * 16 + warp;
    const uint4* Wr = (const uint4*)(g_W8 + (size_t)row * HID);   // 16 weights/load
    float acc = 0.f;
#pragma unroll 8
    for (int i = lane; i < HID / 16; i += 32) {
        uint4 wv = Wr[i];
        const float* hp = &sh[16 * i];
        float2 f;
        f = fp8x2_to_f2((unsigned short)(wv.x & 0xffffu)); acc += f.x * hp[0]  + f.y * hp[1];
        f = fp8x2_to_f2((unsigned short)(wv.x >> 16));     acc += f.x * hp[2]  + f.y * hp[3];
        f = fp8x2_to_f2((unsigned short)(wv.y & 0xffffu)); acc += f.x * hp[4]  + f.y * hp[5];
        f = fp8x2_to_f2((unsigned short)(wv.y >> 16));     acc += f.x * hp[6]  + f.y * hp[7];
        f = fp8x2_to_f2((unsigned short)(wv.z & 0xffffu)); acc += f.x * hp[8]  + f.y * hp[9];
        f = fp8x2_to_f2((unsigned short)(wv.z >> 16));     acc += f.x * hp[10] + f.y * hp[11];
        f = fp8x2_to_f2((unsigned short)(wv.w & 0xffffu)); acc += f.x * hp[12] + f.y * hp[13];
        f = fp8x2_to_f2((unsigned short)(wv.w >> 16));     acc += f.x * hp[14] + f.y * hp[15];
    }
#pragma unroll
    for (int o = 16; o; o >>= 1) acc += __shfl_down_sync(0xffffffffu, acc, o);
    if (lane == 0) g_vA[row] = sigm(a[row] + acc);
}

// ---------------- cheap phase: samples 1..15 (R14 winner, untouched) ----------------

__device__ __forceinline__ float2 blockdot2(float a, float b) {
    __shared__ float ra[32], rb[32], bc[2];
#pragma unroll
    for (int o = 16; o; o >>= 1) {
        a += __shfl_down_sync(0xffffffffu, a, o);
        b += __shfl_down_sync(0xffffffffu, b, o);
    }
    int w = threadIdx.x >> 5;
    if ((threadIdx.x & 31) == 0) { ra[w] = a; rb[w] = b; }
    __syncthreads();
    if (threadIdx.x < 32) {
        float x = ra[threadIdx.x], y = rb[threadIdx.x];
#pragma unroll
        for (int o = 16; o; o >>= 1) {
            x += __shfl_down_sync(0xffffffffu, x, o);
            y += __shfl_down_sync(0xffffffffu, y, o);
        }
        if (threadIdx.x == 0) { bc[0] = x; bc[1] = y; }
    }
    __syncthreads();
    float2 r; r.x = bc[0]; r.y = bc[1];
    return r;
}

__global__ void __launch_bounds__(CTH, 1) k_cheap(const float* __restrict__ inp,
                                                  float* __restrict__ out) {
    const int tid = threadIdx.x;
    float rq[HPT], rs[HPT], rqn[HPT], rsn[HPT], rr[VPT];

#pragma unroll
    for (int jj = 0; jj < HPT; jj++) {
        rq[jj] = g_hA[tid + jj * CTH];
        rs[jj] = g_hB[tid + jj * CTH];
    }
#pragma unroll
    for (int kk = 0; kk < VPT; kk++) rr[kk] = g_vA[tid + kk * CTH];

    float2 dv;
    {
        float a1 = 0.f, a2 = 0.f;
#pragma unroll
        for (int kk = 0; kk < VPT; kk++) {
            int k = tid + kk * CTH;
            float x1v = inp[FLAT + k];
            a1 += inp[k] * x1v;
            a2 += rr[kk] * x1v;
        }
        dv = blockdot2(a1, a2);
    }

#pragma unroll 1
    for (int i = 1; i < NS; i++) {
        const float* p  = inp + (size_t)(i - 1) * FLAT;
        const float* pn = inp + (size_t)i * FLAT;
        const float* xn = pn + FLAT;

#pragma unroll 1
        for (int t = 1; t <= KST; t++) {
            float c1 = LRh * (1.f + dv.x), c2 = LRh * (1.f + dv.y);
            float a3 = 0.f, a4 = 0.f;
#pragma unroll
            for (int jj = 0; jj < HPT; jj++) {
                float th = tanha(rq[jj] * c1 - rs[jj] * c2);
                float h = fmaf(0.5f, th, 0.5f);
                if (t == 1) rqn[jj] = h;
                if (t == KST) rsn[jj] = h;
                a3 += rq[jj] * h;
                a4 += rs[jj] * h;
            }
            float2 dh = blockdot2(a3, a4);

            float c3 = LRh * (1.f + dh.x), c4 = LRh * (1.f + dh.y);
            float a1 = 0.f, a2 = 0.f;
            if (t < KST) {
#pragma unroll
                for (int kk = 0; kk < VPT; kk++) {
                    int k = tid + kk * CTH;
                    float pk = p[k];
                    float v = fmaf(0.5f, tanha(pk * c3 - rr[kk] * c4), 0.5f);
                    a1 += pk * v;
                    a2 += rr[kk] * v;
                }
            } else if (i < NS - 1) {
#pragma unroll
                for (int kk = 0; kk < VPT; kk++) {
                    int k = tid + kk * CTH;
                    float v = fmaf(0.5f, tanha(p[k] * c3 - rr[kk] * c4), 0.5f);
                    rr[kk] = v;
                    float xnk = xn[k];
                    a1 += pn[k] * xnk;
                    a2 += v * xnk;
                }
            } else {
                // final reconstruction: exact sigmoid (no approx error in out)
                float e3 = LRf * (1.f + dh.x), e4 = LRf * (1.f + dh.y);
#pragma unroll
                for (int kk = 0; kk < VPT; kk++) {
                    int k = tid + kk * CTH;
                    float v = sigm(p[k] * e3 - rr[kk] * e4);
                    out[k] = v;
                }
            }
            dv = blockdot2(a1, a2);
        }
#pragma unroll
        for (int jj = 0; jj < HPT; jj++) { rq[jj] = rqn[jj]; rs[jj] = rsn[jj]; }
    }
}

// ---------------- launch ----------------

extern "C" void kernel_launch(void* const* d_in, const int* in_sizes, int n_in,
                              void* d_out, int out_size) {
    const float* inp = (const float*)d_in[0];  // (16, 64, 64, 3) = 16 x 12288
    const float* W   = (const float*)d_in[1];  // (12288, 4096)
    const float* a   = (const float*)d_in[2];  // (12288, 1)
    const float* b   = (const float*)d_in[3];  // (4096, 1)
    float* out = (float*)d_out;                // (12288, 1)

    float* vA = 0;
    cudaGetSymbolAddress((void**)&vA, g_vA);

    for (int s = 0; s < KST; s++) {
        if (s == 0) {
            dim3 g1(HID / 512, RCH1);
            k_gemvT_conv<<<g1, 256>>>(W, inp);       // fused fp8 conversion
            k_hred<<<HID / 256, 256>>>(b, 1, RCH1);
        } else {
            dim3 g2(HID / 1024, RCH2);
            k_gemvT<<<g2, 256>>>(vA);
            k_hred<<<HID / 256, 256>>>(b, (s == KST - 1) ? 2 : 0, RCH2);
        }
        k_gemv<<<FLAT / 16, 512>>>(a);
    }
    k_cheap<<<1, CTH>>>(inp, out);
}

// round 16
// speedup vs baseline: 1.3027x; 1.3027x over previous
#include <cuda_runtime.h>
#include <cuda_fp16.h>
#include <cuda_fp8.h>

#define FLAT 12288
#define HID  4096
#define NS   16
#define KST  4
#define LRf  0.01f
#define LRh  0.005f      // 0.5 * LR, folded into tanh-form sigmoid
#define RCH1 96          // 128-row chunks in fused conv pass
#define RCH2 192         // 64-row chunks in fp8 gemvT passes
#define WSCL 128.f       // fp8 storage scale (W*128); 1/128 folded into v/h
#define WINV (1.f / 128.f)
#define CTH  1024        // cheap-phase threads (single block)
#define VPT  (FLAT / CTH)   // 12 v-elements per thread
#define HPT  (HID / CTH)    // 4 h-elements per thread

// ---------------- device scratch (static, no runtime allocation) ----------------
__device__ unsigned char g_W8[(size_t)FLAT * HID];  // fp8 e4m3 copy of 128*W (48 MB)
__device__ float g_part[RCH2 * HID];  // gemvT partial column sums
__device__ float g_h[HID];            // dense-phase working h
__device__ float g_hA[HID];           // hinit_0 (q)
__device__ float g_hB[HID];           // hfinal_0 (s)
__device__ float g_vA[FLAT];          // vfinal_0 (r)

__device__ __forceinline__ float sigm(float x) { return 1.f / (1.f + __expf(-x)); }
__device__ __forceinline__ float tanha(float x) {
    float y;
    asm("tanh.approx.f32 %0, %1;" : "=f"(y) : "f"(x));
    return y;
}
__device__ __forceinline__ __half2 fp8x2_to_h2(unsigned short s) {
    __half2_raw hr = __nv_cvt_fp8x2_to_halfraw2((__nv_fp8x2_storage_t)s, __NV_E4M3);
    return *reinterpret_cast<__half2*>(&hr);
}
__device__ __forceinline__ __half2 u2h2(unsigned u) {
    return *reinterpret_cast<__half2*>(&u);
}

// ---------------- dense phase: sample 0 ----------------

// Pass 1 of gemvT, fused with W->fp8 conversion: reads fp32 W (200MB) once,
// emits fp8 copy of 128*W (48MB) and partial column sums (fp32 math). grid (8,96).
__global__ void k_gemvT_conv(const float* __restrict__ W, const float* __restrict__ v) {
    __shared__ float sv[128];
    int r0 = blockIdx.y * 128;
    if (threadIdx.x < 128) sv[threadIdx.x] = v[r0 + threadIdx.x];
    __syncthreads();
    int col2 = blockIdx.x * 256 + threadIdx.x;      // 2-col group index
    const float2* Wp = (const float2*)W + (size_t)r0 * (HID / 2) + col2;
    unsigned short* W8p = (unsigned short*)g_W8 + (size_t)r0 * (HID / 2) + col2;
    float ax = 0.f, ay = 0.f;
#pragma unroll 8
    for (int r = 0; r < 128; r++) {
        float2 w = Wp[(size_t)r * (HID / 2)];
        float2 wsc; wsc.x = w.x * WSCL; wsc.y = w.y * WSCL;
        W8p[(size_t)r * (HID / 2)] =
            (unsigned short)__nv_cvt_float2_to_fp8x2(wsc, __NV_SATFINITE, __NV_E4M3);
        float s = sv[r];
        ax += w.x * s;
        ay += w.y * s;
    }
    float2 o; o.x = ax; o.y = ay;
    ((float2*)g_part)[blockIdx.y * (HID / 2) + col2] = o;
}

// Passes 2..4: fp8 W with HFMA2 math. sv pre-packed as half2(s,s), s scaled 1/128.
// Thread handles 4 columns (1 uint/row) over 64 rows. grid (4, 192) = 768 blocks.
__global__ void k_gemvT(const float* __restrict__ v) {
    __shared__ __half2 sv2[64];
    int r0 = blockIdx.y * 64;
    if (threadIdx.x < 64) sv2[threadIdx.x] = __float2half2_rn(v[r0 + threadIdx.x] * WINV);
    __syncthreads();
    int col4 = blockIdx.x * 256 + threadIdx.x;      // 4-col group index
    const unsigned* Wp = (const unsigned*)g_W8 + (size_t)r0 * (HID / 4) + col4;
    __half2 acc0 = __float2half2_rn(0.f), acc1 = acc0;
#pragma unroll 8
    for (int r = 0; r < 64; r++) {
        unsigned w = Wp[(size_t)r * (HID / 4)];
        __half2 s2 = sv2[r];
        acc0 = __hfma2(fp8x2_to_h2((unsigned short)(w & 0xffffu)), s2, acc0);
        acc1 = __hfma2(fp8x2_to_h2((unsigned short)(w >> 16)), s2, acc1);
    }
    float2 f0 = __half22float2(acc0), f1 = __half22float2(acc1);
    float4 o; o.x = f0.x; o.y = f0.y; o.z = f1.x; o.w = f1.y;
    ((float4*)g_part)[blockIdx.y * (HID / 4) + col4] = o;
}

// reduce partials + bias + sigmoid -> g_h; optionally save hinit/hfinal
__global__ void k_hred(const float* __restrict__ b, int save, int nch) {
    int j = blockIdx.x * 256 + threadIdx.x;
    float s = b[j];
#pragma unroll 8
    for (int r = 0; r < nch; r++) s += g_part[r * HID + j];
    float h = sigm(s);
    g_h[j] = h;
    if (save == 1) g_hA[j] = h;        // hinit_0 (q for sample 1)
    else if (save == 2) g_hB[j] = h;   // hfinal_0 (s for sample 1)
}

// v = sigmoid(a + W h): one warp per row, 16 rows per 512-thread block.
// fp8 weights, HFMA2 against h pre-packed as half2 (scaled 1/128) in smem.
// Cross-lane reduction stays fp32.
__global__ void k_gemv(const float* __restrict__ a) {
    __shared__ __half2 sh2[HID / 2];
    for (int k = threadIdx.x; k < HID / 2; k += blockDim.x)
        sh2[k] = __floats2half2_rn(g_h[2 * k] * WINV, g_h[2 * k + 1] * WINV);
    __syncthreads();
    int warp = threadIdx.x >> 5, lane = threadIdx.x & 31;
    int row = blockIdx.x * 16 + warp;
    const uint4* Wr = (const uint4*)(g_W8 + (size_t)row * HID);   // 16 weights/load
    __half2 acc0 = __float2half2_rn(0.f), acc1 = acc0;
#pragma unroll 4
    for (int i = lane; i < HID / 16; i += 32) {
        uint4 wv = Wr[i];
        const uint4* hp = (const uint4*)&sh2[8 * i];   // 8 half2 = 2 x uint4
        uint4 h0 = hp[0], h1 = hp[1];
        acc0 = __hfma2(fp8x2_to_h2((unsigned short)(wv.x & 0xffffu)), u2h2(h0.x), acc0);
        acc1 = __hfma2(fp8x2_to_h2((unsigned short)(wv.x >> 16)),     u2h2(h0.y), acc1);
        acc0 = __hfma2(fp8x2_to_h2((unsigned short)(wv.y & 0xffffu)), u2h2(h0.z), acc0);
        acc1 = __hfma2(fp8x2_to_h2((unsigned short)(wv.y >> 16)),     u2h2(h0.w), acc1);
        acc0 = __hfma2(fp8x2_to_h2((unsigned short)(wv.z & 0xffffu)), u2h2(h1.x), acc0);
        acc1 = __hfma2(fp8x2_to_h2((unsigned short)(wv.z >> 16)),     u2h2(h1.y), acc1);
        acc0 = __hfma2(fp8x2_to_h2((unsigned short)(wv.w & 0xffffu)), u2h2(h1.z), acc0);
        acc1 = __hfma2(fp8x2_to_h2((unsigned short)(wv.w >> 16)),     u2h2(h1.w), acc1);
    }
    float2 r0 = __half22float2(acc0), r1 = __half22float2(acc1);
    float acc = (r0.x + r0.y) + (r1.x + r1.y);
#pragma unroll
    for (int o = 16; o; o >>= 1) acc += __shfl_down_sync(0xffffffffu, acc, o);
    if (lane == 0) g_vA[row] = sigm(a[row] + acc);
}

// ---------------- cheap phase: samples 1..15 (R14 winner, untouched) ----------------

__device__ __forceinline__ float2 blockdot2(float a, float b) {
    __shared__ float ra[32], rb[32], bc[2];
#pragma unroll
    for (int o = 16; o; o >>= 1) {
        a += __shfl_down_sync(0xffffffffu, a, o);
        b += __shfl_down_sync(0xffffffffu, b, o);
    }
    int w = threadIdx.x >> 5;
    if ((threadIdx.x & 31) == 0) { ra[w] = a; rb[w] = b; }
    __syncthreads();
    if (threadIdx.x < 32) {
        float x = ra[threadIdx.x], y = rb[threadIdx.x];
#pragma unroll
        for (int o = 16; o; o >>= 1) {
            x += __shfl_down_sync(0xffffffffu, x, o);
            y += __shfl_down_sync(0xffffffffu, y, o);
        }
        if (threadIdx.x == 0) { bc[0] = x; bc[1] = y; }
    }
    __syncthreads();
    float2 r; r.x = bc[0]; r.y = bc[1];
    return r;
}

__global__ void __launch_bounds__(CTH, 1) k_cheap(const float* __restrict__ inp,
                                                  float* __restrict__ out) {
    const int tid = threadIdx.x;
    float rq[HPT], rs[HPT], rqn[HPT], rsn[HPT], rr[VPT];

#pragma unroll
    for (int jj = 0; jj < HPT; jj++) {
        rq[jj] = g_hA[tid + jj * CTH];
        rs[jj] = g_hB[tid + jj * CTH];
    }
#pragma unroll
    for (int kk = 0; kk < VPT; kk++) rr[kk] = g_vA[tid + kk * CTH];

    float2 dv;
    {
        float a1 = 0.f, a2 = 0.f;
#pragma unroll
        for (int kk = 0; kk < VPT; kk++) {
            int k = tid + kk * CTH;
            float x1v = inp[FLAT + k];
            a1 += inp[k] * x1v;
            a2 += rr[kk] * x1v;
        }
        dv = blockdot2(a1, a2);
    }

#pragma unroll 1
    for (int i = 1; i < NS; i++) {
        const float* p  = inp + (size_t)(i - 1) * FLAT;
        const float* pn = inp + (size_t)i * FLAT;
        const float* xn = pn + FLAT;

#pragma unroll 1
        for (int t = 1; t <= KST; t++) {
            float c1 = LRh * (1.f + dv.x), c2 = LRh * (1.f + dv.y);
            float a3 = 0.f, a4 = 0.f;
#pragma unroll
            for (int jj = 0; jj < HPT; jj++) {
                float th = tanha(rq[jj] * c1 - rs[jj] * c2);
                float h = fmaf(0.5f, th, 0.5f);
                if (t == 1) rqn[jj] = h;
                if (t == KST) rsn[jj] = h;
                a3 += rq[jj] * h;
                a4 += rs[jj] * h;
            }
            float2 dh = blockdot2(a3, a4);

            float c3 = LRh * (1.f + dh.x), c4 = LRh * (1.f + dh.y);
            float a1 = 0.f, a2 = 0.f;
            if (t < KST) {
#pragma unroll
                for (int kk = 0; kk < VPT; kk++) {
                    int k = tid + kk * CTH;
                    float pk = p[k];
                    float v = fmaf(0.5f, tanha(pk * c3 - rr[kk] * c4), 0.5f);
                    a1 += pk * v;
                    a2 += rr[kk] * v;
                }
            } else if (i < NS - 1) {
#pragma unroll
                for (int kk = 0; kk < VPT; kk++) {
                    int k = tid + kk * CTH;
                    float v = fmaf(0.5f, tanha(p[k] * c3 - rr[kk] * c4), 0.5f);
                    rr[kk] = v;
                    float xnk = xn[k];
                    a1 += pn[k] * xnk;
                    a2 += v * xnk;
                }
            } else {
                // final reconstruction: exact sigmoid (no approx error in out)
                float e3 = LRf * (1.f + dh.x), e4 = LRf * (1.f + dh.y);
#pragma unroll
                for (int kk = 0; kk < VPT; kk++) {
                    int k = tid + kk * CTH;
                    float v = sigm(p[k] * e3 - rr[kk] * e4);
                    out[k] = v;
                }
            }
            dv = blockdot2(a1, a2);
        }
#pragma unroll
        for (int jj = 0; jj < HPT; jj++) { rq[jj] = rqn[jj]; rs[jj] = rsn[jj]; }
    }
}

// ---------------- launch ----------------

extern "C" void kernel_launch(void* const* d_in, const int* in_sizes, int n_in,
                              void* d_out, int out_size) {
    const float* inp = (const float*)d_in[0];  // (16, 64, 64, 3) = 16 x 12288
    const float* W   = (const float*)d_in[1];  // (12288, 4096)
    const float* a   = (const float*)d_in[2];  // (12288, 1)
    const float* b   = (const float*)d_in[3];  // (4096, 1)
    float* out = (float*)d_out;                // (12288, 1)

    float* vA = 0;
    cudaGetSymbolAddress((void**)&vA, g_vA);

    for (int s = 0; s < KST; s++) {
        if (s == 0) {
            dim3 g1(HID / 512, RCH1);
            k_gemvT_conv<<<g1, 256>>>(W, inp);       // fused fp8 conversion
            k_hred<<<HID / 256, 256>>>(b, 1, RCH1);
        } else {
            dim3 g2(HID / 1024, RCH2);
            k_gemvT<<<g2, 256>>>(vA);
            k_hred<<<HID / 256, 256>>>(b, (s == KST - 1) ? 2 : 0, RCH2);
        }
        k_gemv<<<FLAT / 16, 512>>>(a);
    }
    k_cheap<<<1, CTH>>>(inp, out);
}